// round 15
// baseline (speedup 1.0000x reference)
#include <cuda_runtime.h>
#include <cuda_bf16.h>
#include <cstdint>

// ---------------------------------------------------------------------------
// Problem constants
// ---------------------------------------------------------------------------
#define N_TOK   8192
#define D_MODEL 2048
#define VOCAB   50257
#define IGNORE_INDEX (-100)

#define TILE_M 128
#define TILE_N 128
#define KCH    64                      // bf16 K elements per pipeline stage (128 B rows)
#define NCHUNK (D_MODEL / KCH)         // 32
#define NSTG   3

#define M_TILES (N_TOK / TILE_M)                 // 64
#define V_TILES ((VOCAB + TILE_N - 1) / TILE_N)  // 393
#define C_ROWS_PAD (V_TILES * TILE_N)            // 50304 (padded vocab rows)

#define STAGE_BYTES ((TILE_M + TILE_N) * 128)    // 32768
#define SMEM_TOTAL  (NSTG * STAGE_BYTES)         // 98304 -> 2 CTAs/SM

// ---------------------------------------------------------------------------
// Device scratch (static — no allocations allowed)
// ---------------------------------------------------------------------------
__device__ __align__(1024) __nv_bfloat16 g_e_bf[(size_t)N_TOK * D_MODEL];
__device__ __align__(1024) __nv_bfloat16 g_c_bf[(size_t)C_ROWS_PAD * D_MODEL];
// token-major partials: one (max, sumexp) per (token, v_tile)
__device__ float g_pm[(size_t)N_TOK * V_TILES];
__device__ float g_ps[(size_t)N_TOK * V_TILES];
__device__ float g_tgt[N_TOK];                  // exact fp32 target logits
__device__ float g_bsum[1024];
__device__ int   g_bcnt[1024];

// ---------------------------------------------------------------------------
// Base-arch PTX helpers (valid on compute_103)
// ---------------------------------------------------------------------------
__device__ __forceinline__ uint32_t smem_u32(const void* p) {
    uint32_t a;
    asm("{ .reg .u64 t; cvta.to.shared.u64 t, %1; cvt.u32.u64 %0, t; }"
        : "=r"(a) : "l"(p));
    return a;
}

__device__ __forceinline__ void cp_async16(uint32_t saddr, const void* gaddr) {
    asm volatile("cp.async.cg.shared.global [%0], [%1], 16;"
                 :: "r"(saddr), "l"(gaddr) : "memory");
}
#define CP_COMMIT() asm volatile("cp.async.commit_group;" ::: "memory")
#define CP_WAIT(n)  asm volatile("cp.async.wait_group %0;" :: "n"(n) : "memory")

__device__ __forceinline__ void ldmatrix_x4(uint32_t& r0, uint32_t& r1,
                                            uint32_t& r2, uint32_t& r3, uint32_t addr) {
    asm volatile("ldmatrix.sync.aligned.m8n8.x4.shared.b16 {%0,%1,%2,%3}, [%4];"
                 : "=r"(r0), "=r"(r1), "=r"(r2), "=r"(r3) : "r"(addr));
}

__device__ __forceinline__ void mma_bf16(float& d0, float& d1, float& d2, float& d3,
                                         uint32_t a0, uint32_t a1, uint32_t a2, uint32_t a3,
                                         uint32_t b0, uint32_t b1) {
    asm volatile(
        "mma.sync.aligned.m16n8k16.row.col.f32.bf16.bf16.f32 "
        "{%0,%1,%2,%3}, {%4,%5,%6,%7}, {%8,%9}, {%0,%1,%2,%3};"
        : "+f"(d0), "+f"(d1), "+f"(d2), "+f"(d3)
        : "r"(a0), "r"(a1), "r"(a2), "r"(a3), "r"(b0), "r"(b1));
}

__device__ __forceinline__ uint2 cvt2(float4 v) {
    __nv_bfloat162 lo = __float22bfloat162_rn(make_float2(v.x, v.y));
    __nv_bfloat162 hi = __float22bfloat162_rn(make_float2(v.z, v.w));
    uint2 p;
    p.x = *reinterpret_cast<uint32_t*>(&lo);
    p.y = *reinterpret_cast<uint32_t*>(&hi);
    return p;
}

// ---------------------------------------------------------------------------
// Kernel 1: fp32 -> bf16 conversion of e and c (+ zero-pad c to C_ROWS_PAD)
// ---------------------------------------------------------------------------
__global__ void convert_kernel(const float4* __restrict__ e4, const float4* __restrict__ c4) {
    const size_t E4 = (size_t)N_TOK * D_MODEL / 4;
    const size_t C4 = (size_t)VOCAB * D_MODEL / 4;
    const size_t P4 = (size_t)C_ROWS_PAD * D_MODEL / 4;
    size_t i0 = (size_t)blockIdx.x * blockDim.x + threadIdx.x;
    size_t stride = (size_t)gridDim.x * blockDim.x;
    uint2* eo = reinterpret_cast<uint2*>(g_e_bf);
    uint2* co = reinterpret_cast<uint2*>(g_c_bf);
    for (size_t i = i0; i < E4; i += stride)  eo[i] = cvt2(e4[i]);
    for (size_t i = i0; i < C4; i += stride)  co[i] = cvt2(c4[i]);
    for (size_t i = C4 + i0; i < P4; i += stride) {
        uint2 z; z.x = 0u; z.y = 0u;
        co[i] = z;
    }
}

// ---------------------------------------------------------------------------
// Kernel 2: exact fp32 target logits (one warp per token) — side stream
// ---------------------------------------------------------------------------
__global__ void tgt_kernel(const float* __restrict__ e, const float* __restrict__ c,
                           const long long* __restrict__ tg) {
    int warp = (blockIdx.x * blockDim.x + threadIdx.x) >> 5;
    int lane = threadIdx.x & 31;
    if (warp >= N_TOK) return;
    long long t = tg[warp];
    float a0 = 0.0f;
    if (t >= 0 && t < VOCAB) {
        const float4* er = reinterpret_cast<const float4*>(e + (size_t)warp * D_MODEL);
        const float4* cr = reinterpret_cast<const float4*>(c + (size_t)t * D_MODEL);
        #pragma unroll 4
        for (int i = lane; i < D_MODEL / 4; i += 32) {
            float4 a = er[i], b = cr[i];
            a0 += a.x * b.x + a.y * b.y + a.z * b.z + a.w * b.w;
        }
    }
    #pragma unroll
    for (int off = 16; off > 0; off >>= 1)
        a0 += __shfl_xor_sync(0xFFFFFFFFu, a0, off);
    if (lane == 0) g_tgt[warp] = a0;
}

// ---------------------------------------------------------------------------
// Kernel 3: bf16 HMMA GEMM tile (128x128xK=2048) + per-row online max/sum-exp
// R8 winner body; mainloop split into hot loop (unconditional loads) + drain
// to remove the per-chunk doload predicate from the 8 cp.async sites.
// ---------------------------------------------------------------------------
__global__ void __launch_bounds__(256, 2)
gemm_lse_kernel() {
    extern __shared__ char smem[];
    const uint32_t sbase = smem_u32(smem);
    const int tid  = threadIdx.x;
    const int wid  = tid >> 5;
    const int lane = tid & 31;
    const int warp_m = wid >> 2;     // 0..1  -> m offset 64*warp_m
    const int warp_n = wid & 3;      // 0..3  -> n offset 32*warp_n
    const int m_tile = blockIdx.x;
    const int v_tile = blockIdx.y;

    // ---- cp.async geometry ----
    const int row0 = tid >> 3;           // 0..31
    const int ch   = tid & 7;            // 0..7
    const __nv_bfloat16* Abase =
        g_e_bf + (size_t)(m_tile * TILE_M + row0) * D_MODEL + ch * 8;
    const __nv_bfloat16* Bbase =
        g_c_bf + (size_t)(v_tile * TILE_N + row0) * D_MODEL + ch * 8;
    const uint32_t sd0 = (uint32_t)(row0 * 128 + ((ch ^ (row0 & 7)) << 4));

    // ---- ldmatrix geometry ----
    const int lx = lane & 7;
    const int a_row = warp_m * 64 + (lane & 15);
    const int b_row = TILE_M + warp_n * 32 + (lane & 7) + (((lane >> 4) & 1) << 3);
    const int a_ch_add = (lane >> 4) & 1;
    const int b_ch_add = (lane >> 3) & 1;

    float acc[4][4][4];
    #pragma unroll
    for (int mf = 0; mf < 4; mf++)
        #pragma unroll
        for (int nf = 0; nf < 4; nf++)
            #pragma unroll
            for (int c = 0; c < 4; c++) acc[mf][nf][c] = 0.0f;

    // ---- prologue: fill NSTG-1 = 2 stages ----
    #pragma unroll
    for (int s = 0; s < NSTG - 1; s++) {
        uint32_t sb = sbase + s * STAGE_BYTES + sd0;
        #pragma unroll
        for (int t = 0; t < 4; t++)
            cp_async16(sb + 4096 * t, Abase + (size_t)t * 32 * D_MODEL + s * KCH);
        #pragma unroll
        for (int t = 0; t < 4; t++)
            cp_async16(sb + 16384 + 4096 * t, Bbase + (size_t)t * 32 * D_MODEL + s * KCH);
        CP_COMMIT();
    }

    // ---- mainloop (hot): chunks 0..29, loads unconditional ----
    int sc = 0;              // compute stage
    int sl = NSTG - 1;       // stage to load next
    #pragma unroll 1
    for (int kt = 0; kt < NCHUNK - (NSTG - 1); kt++) {
        CP_WAIT(NSTG - 2);
        __syncthreads();

        const int kn = kt + NSTG - 1;
        const uint32_t sb  = sbase + sl * STAGE_BYTES + sd0;
        const uint32_t stg = sbase + sc * STAGE_BYTES;

        #pragma unroll
        for (int ks = 0; ks < 4; ks++) {
            // interleave 2 of the 8 cp.async issues per ks iteration
            cp_async16(sb + 4096 * ks,
                       Abase + (size_t)ks * 32 * D_MODEL + kn * KCH);
            cp_async16(sb + 16384 + 4096 * ks,
                       Bbase + (size_t)ks * 32 * D_MODEL + kn * KCH);
            uint32_t a[4][4];
            #pragma unroll
            for (int mf = 0; mf < 4; mf++) {
                int row = a_row + mf * 16;
                uint32_t addr = stg + row * 128 + ((((ks << 1) + a_ch_add) ^ lx) << 4);
                ldmatrix_x4(a[mf][0], a[mf][1], a[mf][2], a[mf][3], addr);
            }
            uint32_t b[2][4];
            #pragma unroll
            for (int nf2 = 0; nf2 < 2; nf2++) {
                int row = b_row + nf2 * 16;
                uint32_t addr = stg + row * 128 + ((((ks << 1) + b_ch_add) ^ lx) << 4);
                ldmatrix_x4(b[nf2][0], b[nf2][1], b[nf2][2], b[nf2][3], addr);
            }
            #pragma unroll
            for (int mf = 0; mf < 4; mf++)
                #pragma unroll
                for (int nf = 0; nf < 4; nf++) {
                    uint32_t b0 = b[nf >> 1][(nf & 1) * 2];
                    uint32_t b1 = b[nf >> 1][(nf & 1) * 2 + 1];
                    mma_bf16(acc[mf][nf][0], acc[mf][nf][1], acc[mf][nf][2], acc[mf][nf][3],
                             a[mf][0], a[mf][1], a[mf][2], a[mf][3], b0, b1);
                }
        }
        CP_COMMIT();
        sc = (sc == NSTG - 1) ? 0 : sc + 1;
        sl = (sl == NSTG - 1) ? 0 : sl + 1;
    }

    // ---- drain: last NSTG-1 = 2 chunks, no loads ----
    #pragma unroll 1
    for (int kt = 0; kt < NSTG - 1; kt++) {
        CP_WAIT(NSTG - 2);
        __syncthreads();
        const uint32_t stg = sbase + sc * STAGE_BYTES;
        #pragma unroll
        for (int ks = 0; ks < 4; ks++) {
            uint32_t a[4][4];
            #pragma unroll
            for (int mf = 0; mf < 4; mf++) {
                int row = a_row + mf * 16;
                uint32_t addr = stg + row * 128 + ((((ks << 1) + a_ch_add) ^ lx) << 4);
                ldmatrix_x4(a[mf][0], a[mf][1], a[mf][2], a[mf][3], addr);
            }
            uint32_t b[2][4];
            #pragma unroll
            for (int nf2 = 0; nf2 < 2; nf2++) {
                int row = b_row + nf2 * 16;
                uint32_t addr = stg + row * 128 + ((((ks << 1) + b_ch_add) ^ lx) << 4);
                ldmatrix_x4(b[nf2][0], b[nf2][1], b[nf2][2], b[nf2][3], addr);
            }
            #pragma unroll
            for (int mf = 0; mf < 4; mf++)
                #pragma unroll
                for (int nf = 0; nf < 4; nf++) {
                    uint32_t b0 = b[nf >> 1][(nf & 1) * 2];
                    uint32_t b1 = b[nf >> 1][(nf & 1) * 2 + 1];
                    mma_bf16(acc[mf][nf][0], acc[mf][nf][1], acc[mf][nf][2], acc[mf][nf][3],
                             a[mf][0], a[mf][1], a[mf][2], a[mf][3], b0, b1);
                }
        }
        CP_COMMIT();
        sc = (sc == NSTG - 1) ? 0 : sc + 1;
    }

    // ---- epilogue: per-warp (max, sumexp) per row over its 32 cols,
    //      then combine the 4 warp-columns in smem -> one partial per row ----
    const int vb = v_tile * TILE_N + warp_n * 32;
    const bool edge = (vb + 32 > VOCAB);

    __syncthreads();                       // stage smem now reusable
    float* cm = reinterpret_cast<float*>(smem);        // [128][4]
    float* cs = cm + 128 * 4;                          // [128][4]

    #pragma unroll
    for (int mf = 0; mf < 4; mf++) {
        float mlo = -INFINITY, mhi = -INFINITY;
        #pragma unroll
        for (int nf = 0; nf < 4; nf++) {
            #pragma unroll
            for (int c = 0; c < 2; c++) {
                int col = vb + nf * 8 + (lane & 3) * 2 + c;
                bool ok = !edge || (col < VOCAB);
                if (ok) {
                    mlo = fmaxf(mlo, acc[mf][nf][c]);
                    mhi = fmaxf(mhi, acc[mf][nf][2 + c]);
                }
            }
        }
        mlo = fmaxf(mlo, __shfl_xor_sync(0xFFFFFFFFu, mlo, 1));
        mlo = fmaxf(mlo, __shfl_xor_sync(0xFFFFFFFFu, mlo, 2));
        mhi = fmaxf(mhi, __shfl_xor_sync(0xFFFFFFFFu, mhi, 1));
        mhi = fmaxf(mhi, __shfl_xor_sync(0xFFFFFFFFu, mhi, 2));

        float slo = 0.0f, shi = 0.0f;
        #pragma unroll
        for (int nf = 0; nf < 4; nf++) {
            #pragma unroll
            for (int c = 0; c < 2; c++) {
                int col = vb + nf * 8 + (lane & 3) * 2 + c;
                bool ok = !edge || (col < VOCAB);
                if (ok) {
                    slo += __expf(acc[mf][nf][c] - mlo);
                    shi += __expf(acc[mf][nf][2 + c] - mhi);
                }
            }
        }
        slo += __shfl_xor_sync(0xFFFFFFFFu, slo, 1);
        slo += __shfl_xor_sync(0xFFFFFFFFu, slo, 2);
        shi += __shfl_xor_sync(0xFFFFFFFFu, shi, 1);
        shi += __shfl_xor_sync(0xFFFFFFFFu, shi, 2);

        if ((lane & 3) == 0) {
            int r = warp_m * 64 + mf * 16 + (lane >> 2);
            cm[r * 4 + warp_n]       = mlo;
            cs[r * 4 + warp_n]       = slo;
            cm[(r + 8) * 4 + warp_n] = mhi;
            cs[(r + 8) * 4 + warp_n] = shi;
        }
    }
    __syncthreads();

    if (tid < 128) {
        float M = -INFINITY;
        #pragma unroll
        for (int w = 0; w < 4; w++) M = fmaxf(M, cm[tid * 4 + w]);
        float S = 0.0f;
        #pragma unroll
        for (int w = 0; w < 4; w++) {
            float s = cs[tid * 4 + w];
            if (s > 0.0f) S += s * __expf(cm[tid * 4 + w] - M);
        }
        size_t gr = (size_t)(m_tile * TILE_M + tid);
        g_pm[gr * V_TILES + v_tile] = M;
        g_ps[gr * V_TILES + v_tile] = S;
    }
}

// ---------------------------------------------------------------------------
// Kernel 4: one warp per token; lanes stride over V_TILES partials (coalesced)
// ---------------------------------------------------------------------------
__global__ void reduce_kernel(const long long* __restrict__ tg) {
    const int tid  = threadIdx.x;
    const int lane = tid & 31;
    const int wib  = tid >> 5;                       // warp in block (0..7)
    const int tok  = blockIdx.x * 8 + wib;           // 1024 blocks x 8 warps

    float nll = 0.0f;
    int valid = 0;
    long long t = tg[tok];
    if (t != IGNORE_INDEX) {
        const float* pm = g_pm + (size_t)tok * V_TILES;
        const float* ps = g_ps + (size_t)tok * V_TILES;
        float M = -INFINITY;
        for (int j = lane; j < V_TILES; j += 32) M = fmaxf(M, pm[j]);
        #pragma unroll
        for (int off = 16; off > 0; off >>= 1)
            M = fmaxf(M, __shfl_xor_sync(0xFFFFFFFFu, M, off));
        float S = 0.0f;
        for (int j = lane; j < V_TILES; j += 32) {
            float s = ps[j];
            if (s > 0.0f) S += s * __expf(pm[j] - M);
        }
        #pragma unroll
        for (int off = 16; off > 0; off >>= 1)
            S += __shfl_xor_sync(0xFFFFFFFFu, S, off);
        nll = M + logf(S) - g_tgt[tok];
        valid = 1;
    }
    __shared__ float bs[8];
    __shared__ int   bc[8];
    if (lane == 0) { bs[wib] = nll; bc[wib] = valid; }
    __syncthreads();
    if (tid == 0) {
        float s = 0.0f; int c = 0;
        #pragma unroll
        for (int w = 0; w < 8; w++) { s += bs[w]; c += bc[w]; }
        g_bsum[blockIdx.x] = s;
        g_bcnt[blockIdx.x] = c;
    }
}

__global__ void finalize_kernel(float* out) {
    __shared__ float s[1024];
    __shared__ int   c[1024];
    int tid = threadIdx.x;
    s[tid] = g_bsum[tid]; c[tid] = g_bcnt[tid];
    __syncthreads();
    for (int o = 512; o > 0; o >>= 1) {
        if (tid < o) { s[tid] += s[tid + o]; c[tid] += c[tid + o]; }
        __syncthreads();
    }
    if (tid == 0) out[0] = s[0] / (float)max(c[0], 1);
}

// ---------------------------------------------------------------------------
extern "C" void kernel_launch(void* const* d_in, const int* in_sizes, int n_in,
                              void* d_out, int out_size) {
    (void)in_sizes; (void)n_in; (void)out_size;
    const float*     e  = (const float*)d_in[0];
    const float*     c  = (const float*)d_in[1];
    const long long* tg = (const long long*)d_in[2];
    float* out = (float*)d_out;

    static cudaStream_t s2 = nullptr;
    static cudaEvent_t ev_fork = nullptr, ev_join = nullptr;
    if (s2 == nullptr) {
        cudaStreamCreateWithFlags(&s2, cudaStreamNonBlocking);
        cudaEventCreateWithFlags(&ev_fork, cudaEventDisableTiming);
        cudaEventCreateWithFlags(&ev_join, cudaEventDisableTiming);
        cudaFuncSetAttribute(gemm_lse_kernel,
                             cudaFuncAttributeMaxDynamicSharedMemorySize, SMEM_TOTAL);
        cudaFuncSetAttribute(gemm_lse_kernel,
                             cudaFuncAttributePreferredSharedMemoryCarveout, 100);
    }

    // fork: tgt_kernel depends only on raw fp32 inputs -> side stream,
    // overlapping convert + GEMM (GEMM is tensor-bound, DRAM ~1%).
    cudaEventRecord(ev_fork, 0);
    cudaStreamWaitEvent(s2, ev_fork, 0);
    tgt_kernel<<<(N_TOK * 32) / 256, 256, 0, s2>>>(e, c, tg);
    cudaEventRecord(ev_join, s2);

    // main stream: convert -> GEMM
    convert_kernel<<<4096, 256>>>(reinterpret_cast<const float4*>(e),
                                  reinterpret_cast<const float4*>(c));
    gemm_lse_kernel<<<dim3(M_TILES, V_TILES), 256, SMEM_TOTAL>>>();

    // join: reduce needs g_tgt
    cudaStreamWaitEvent(0, ev_join, 0);
    reduce_kernel<<<1024, 256>>>(tg);
    finalize_kernel<<<1, 1024>>>(out);
}

// round 16
// speedup vs baseline: 1.0312x; 1.0312x over previous
#include <cuda_runtime.h>
#include <cuda_bf16.h>
#include <cstdint>

// ---------------------------------------------------------------------------
// Problem constants
// ---------------------------------------------------------------------------
#define N_TOK   8192
#define D_MODEL 2048
#define VOCAB   50257
#define IGNORE_INDEX (-100)

#define TILE_M 128
#define TILE_N 128
#define KCH    64                      // bf16 K elements per pipeline stage (128 B rows)
#define NCHUNK (D_MODEL / KCH)         // 32
#define NSTG   3

#define M_TILES (N_TOK / TILE_M)                 // 64
#define V_TILES ((VOCAB + TILE_N - 1) / TILE_N)  // 393
#define C_ROWS_PAD (V_TILES * TILE_N)            // 50304 (padded vocab rows)

#define STAGE_BYTES ((TILE_M + TILE_N) * 128)    // 32768
#define SMEM_TOTAL  (NSTG * STAGE_BYTES)         // 98304 -> 2 CTAs/SM

// ---------------------------------------------------------------------------
// Device scratch (static — no allocations allowed)
// ---------------------------------------------------------------------------
__device__ __align__(1024) __nv_bfloat16 g_e_bf[(size_t)N_TOK * D_MODEL];
__device__ __align__(1024) __nv_bfloat16 g_c_bf[(size_t)C_ROWS_PAD * D_MODEL];
// token-major partials: one (max, sumexp) per (token, v_tile)
__device__ float g_pm[(size_t)N_TOK * V_TILES];
__device__ float g_ps[(size_t)N_TOK * V_TILES];
__device__ float g_tgt[N_TOK];                  // exact fp32 target logits
__device__ float g_bsum[1024];
__device__ int   g_bcnt[1024];

// ---------------------------------------------------------------------------
// Base-arch PTX helpers (valid on compute_103)
// ---------------------------------------------------------------------------
__device__ __forceinline__ uint32_t smem_u32(const void* p) {
    uint32_t a;
    asm("{ .reg .u64 t; cvta.to.shared.u64 t, %1; cvt.u32.u64 %0, t; }"
        : "=r"(a) : "l"(p));
    return a;
}

__device__ __forceinline__ void cp_async16(uint32_t saddr, const void* gaddr) {
    asm volatile("cp.async.cg.shared.global [%0], [%1], 16;"
                 :: "r"(saddr), "l"(gaddr) : "memory");
}
#define CP_COMMIT() asm volatile("cp.async.commit_group;" ::: "memory")
#define CP_WAIT(n)  asm volatile("cp.async.wait_group %0;" :: "n"(n) : "memory")

__device__ __forceinline__ void ldmatrix_x4(uint32_t& r0, uint32_t& r1,
                                            uint32_t& r2, uint32_t& r3, uint32_t addr) {
    asm volatile("ldmatrix.sync.aligned.m8n8.x4.shared.b16 {%0,%1,%2,%3}, [%4];"
                 : "=r"(r0), "=r"(r1), "=r"(r2), "=r"(r3) : "r"(addr));
}

__device__ __forceinline__ void mma_bf16(float& d0, float& d1, float& d2, float& d3,
                                         uint32_t a0, uint32_t a1, uint32_t a2, uint32_t a3,
                                         uint32_t b0, uint32_t b1) {
    asm volatile(
        "mma.sync.aligned.m16n8k16.row.col.f32.bf16.bf16.f32 "
        "{%0,%1,%2,%3}, {%4,%5,%6,%7}, {%8,%9}, {%0,%1,%2,%3};"
        : "+f"(d0), "+f"(d1), "+f"(d2), "+f"(d3)
        : "r"(a0), "r"(a1), "r"(a2), "r"(a3), "r"(b0), "r"(b1));
}

__device__ __forceinline__ uint2 cvt2(float4 v) {
    __nv_bfloat162 lo = __float22bfloat162_rn(make_float2(v.x, v.y));
    __nv_bfloat162 hi = __float22bfloat162_rn(make_float2(v.z, v.w));
    uint2 p;
    p.x = *reinterpret_cast<uint32_t*>(&lo);
    p.y = *reinterpret_cast<uint32_t*>(&hi);
    return p;
}

// ---------------------------------------------------------------------------
// Kernel 1: fp32 -> bf16 conversion of e and c (+ zero-pad c to C_ROWS_PAD)
// ---------------------------------------------------------------------------
__global__ void convert_kernel(const float4* __restrict__ e4, const float4* __restrict__ c4) {
    const size_t E4 = (size_t)N_TOK * D_MODEL / 4;
    const size_t C4 = (size_t)VOCAB * D_MODEL / 4;
    const size_t P4 = (size_t)C_ROWS_PAD * D_MODEL / 4;
    size_t i0 = (size_t)blockIdx.x * blockDim.x + threadIdx.x;
    size_t stride = (size_t)gridDim.x * blockDim.x;
    uint2* eo = reinterpret_cast<uint2*>(g_e_bf);
    uint2* co = reinterpret_cast<uint2*>(g_c_bf);
    for (size_t i = i0; i < E4; i += stride)  eo[i] = cvt2(e4[i]);
    for (size_t i = i0; i < C4; i += stride)  co[i] = cvt2(c4[i]);
    for (size_t i = C4 + i0; i < P4; i += stride) {
        uint2 z; z.x = 0u; z.y = 0u;
        co[i] = z;
    }
}

// ---------------------------------------------------------------------------
// Kernel 2: exact fp32 target logits (one warp per token) — side stream
// ---------------------------------------------------------------------------
__global__ void tgt_kernel(const float* __restrict__ e, const float* __restrict__ c,
                           const long long* __restrict__ tg) {
    int warp = (blockIdx.x * blockDim.x + threadIdx.x) >> 5;
    int lane = threadIdx.x & 31;
    if (warp >= N_TOK) return;
    long long t = tg[warp];
    float a0 = 0.0f;
    if (t >= 0 && t < VOCAB) {
        const float4* er = reinterpret_cast<const float4*>(e + (size_t)warp * D_MODEL);
        const float4* cr = reinterpret_cast<const float4*>(c + (size_t)t * D_MODEL);
        #pragma unroll 4
        for (int i = lane; i < D_MODEL / 4; i += 32) {
            float4 a = er[i], b = cr[i];
            a0 += a.x * b.x + a.y * b.y + a.z * b.z + a.w * b.w;
        }
    }
    #pragma unroll
    for (int off = 16; off > 0; off >>= 1)
        a0 += __shfl_xor_sync(0xFFFFFFFFu, a0, off);
    if (lane == 0) g_tgt[warp] = a0;
}

// ---------------------------------------------------------------------------
// Kernel 3: bf16 HMMA GEMM tile (128x128xK=2048) + per-row online max/sum-exp
// EXACT R8 WINNER BODY (best measured: 3590 us total). FROZEN.
// 256 threads, 8 warps (2M x 4N), warp tile 64x32, 3-stage cp.async pipeline,
// cp.async interleaved into ks iterations, dynamic stage indices, 2 CTAs/SM.
// ---------------------------------------------------------------------------
__global__ void __launch_bounds__(256, 2)
gemm_lse_kernel() {
    extern __shared__ char smem[];
    const uint32_t sbase = smem_u32(smem);
    const int tid  = threadIdx.x;
    const int wid  = tid >> 5;
    const int lane = tid & 31;
    const int warp_m = wid >> 2;     // 0..1  -> m offset 64*warp_m
    const int warp_n = wid & 3;      // 0..3  -> n offset 32*warp_n
    const int m_tile = blockIdx.x;
    const int v_tile = blockIdx.y;

    // ---- cp.async geometry ----
    const int row0 = tid >> 3;           // 0..31
    const int ch   = tid & 7;            // 0..7
    const __nv_bfloat16* Abase =
        g_e_bf + (size_t)(m_tile * TILE_M + row0) * D_MODEL + ch * 8;
    const __nv_bfloat16* Bbase =
        g_c_bf + (size_t)(v_tile * TILE_N + row0) * D_MODEL + ch * 8;
    const uint32_t sd0 = (uint32_t)(row0 * 128 + ((ch ^ (row0 & 7)) << 4));

    // ---- ldmatrix geometry ----
    const int lx = lane & 7;
    const int a_row = warp_m * 64 + (lane & 15);
    const int b_row = TILE_M + warp_n * 32 + (lane & 7) + (((lane >> 4) & 1) << 3);
    const int a_ch_add = (lane >> 4) & 1;
    const int b_ch_add = (lane >> 3) & 1;

    float acc[4][4][4];
    #pragma unroll
    for (int mf = 0; mf < 4; mf++)
        #pragma unroll
        for (int nf = 0; nf < 4; nf++)
            #pragma unroll
            for (int c = 0; c < 4; c++) acc[mf][nf][c] = 0.0f;

    // ---- prologue: fill NSTG-1 = 2 stages ----
    #pragma unroll
    for (int s = 0; s < NSTG - 1; s++) {
        uint32_t sb = sbase + s * STAGE_BYTES + sd0;
        #pragma unroll
        for (int t = 0; t < 4; t++)
            cp_async16(sb + 4096 * t, Abase + (size_t)t * 32 * D_MODEL + s * KCH);
        #pragma unroll
        for (int t = 0; t < 4; t++)
            cp_async16(sb + 16384 + 4096 * t, Bbase + (size_t)t * 32 * D_MODEL + s * KCH);
        CP_COMMIT();
    }

    // ---- mainloop ----
    int sc = 0;              // compute stage
    int sl = NSTG - 1;       // stage to load next
    for (int kt = 0; kt < NCHUNK; kt++) {
        CP_WAIT(NSTG - 2);
        __syncthreads();

        const int kn = kt + NSTG - 1;
        const bool doload = (kn < NCHUNK);
        const uint32_t sb  = sbase + sl * STAGE_BYTES + sd0;
        const uint32_t stg = sbase + sc * STAGE_BYTES;

        #pragma unroll
        for (int ks = 0; ks < 4; ks++) {
            // interleave 2 of the 8 cp.async issues per ks iteration
            if (doload) {
                cp_async16(sb + 4096 * ks,
                           Abase + (size_t)ks * 32 * D_MODEL + kn * KCH);
                cp_async16(sb + 16384 + 4096 * ks,
                           Bbase + (size_t)ks * 32 * D_MODEL + kn * KCH);
            }
            uint32_t a[4][4];
            #pragma unroll
            for (int mf = 0; mf < 4; mf++) {
                int row = a_row + mf * 16;
                uint32_t addr = stg + row * 128 + ((((ks << 1) + a_ch_add) ^ lx) << 4);
                ldmatrix_x4(a[mf][0], a[mf][1], a[mf][2], a[mf][3], addr);
            }
            uint32_t b[2][4];
            #pragma unroll
            for (int nf2 = 0; nf2 < 2; nf2++) {
                int row = b_row + nf2 * 16;
                uint32_t addr = stg + row * 128 + ((((ks << 1) + b_ch_add) ^ lx) << 4);
                ldmatrix_x4(b[nf2][0], b[nf2][1], b[nf2][2], b[nf2][3], addr);
            }
            #pragma unroll
            for (int mf = 0; mf < 4; mf++)
                #pragma unroll
                for (int nf = 0; nf < 4; nf++) {
                    uint32_t b0 = b[nf >> 1][(nf & 1) * 2];
                    uint32_t b1 = b[nf >> 1][(nf & 1) * 2 + 1];
                    mma_bf16(acc[mf][nf][0], acc[mf][nf][1], acc[mf][nf][2], acc[mf][nf][3],
                             a[mf][0], a[mf][1], a[mf][2], a[mf][3], b0, b1);
                }
        }
        CP_COMMIT();
        sc = (sc == NSTG - 1) ? 0 : sc + 1;
        sl = (sl == NSTG - 1) ? 0 : sl + 1;
    }

    // ---- epilogue: per-warp (max, sumexp) per row over its 32 cols,
    //      then combine the 4 warp-columns in smem -> one partial per row ----
    const int vb = v_tile * TILE_N + warp_n * 32;
    const bool edge = (vb + 32 > VOCAB);

    __syncthreads();                       // stage smem now reusable
    float* cm = reinterpret_cast<float*>(smem);        // [128][4]
    float* cs = cm + 128 * 4;                          // [128][4]

    #pragma unroll
    for (int mf = 0; mf < 4; mf++) {
        float mlo = -INFINITY, mhi = -INFINITY;
        #pragma unroll
        for (int nf = 0; nf < 4; nf++) {
            #pragma unroll
            for (int c = 0; c < 2; c++) {
                int col = vb + nf * 8 + (lane & 3) * 2 + c;
                bool ok = !edge || (col < VOCAB);
                if (ok) {
                    mlo = fmaxf(mlo, acc[mf][nf][c]);
                    mhi = fmaxf(mhi, acc[mf][nf][2 + c]);
                }
            }
        }
        mlo = fmaxf(mlo, __shfl_xor_sync(0xFFFFFFFFu, mlo, 1));
        mlo = fmaxf(mlo, __shfl_xor_sync(0xFFFFFFFFu, mlo, 2));
        mhi = fmaxf(mhi, __shfl_xor_sync(0xFFFFFFFFu, mhi, 1));
        mhi = fmaxf(mhi, __shfl_xor_sync(0xFFFFFFFFu, mhi, 2));

        float slo = 0.0f, shi = 0.0f;
        #pragma unroll
        for (int nf = 0; nf < 4; nf++) {
            #pragma unroll
            for (int c = 0; c < 2; c++) {
                int col = vb + nf * 8 + (lane & 3) * 2 + c;
                bool ok = !edge || (col < VOCAB);
                if (ok) {
                    slo += __expf(acc[mf][nf][c] - mlo);
                    shi += __expf(acc[mf][nf][2 + c] - mhi);
                }
            }
        }
        slo += __shfl_xor_sync(0xFFFFFFFFu, slo, 1);
        slo += __shfl_xor_sync(0xFFFFFFFFu, slo, 2);
        shi += __shfl_xor_sync(0xFFFFFFFFu, shi, 1);
        shi += __shfl_xor_sync(0xFFFFFFFFu, shi, 2);

        if ((lane & 3) == 0) {
            int r = warp_m * 64 + mf * 16 + (lane >> 2);
            cm[r * 4 + warp_n]       = mlo;
            cs[r * 4 + warp_n]       = slo;
            cm[(r + 8) * 4 + warp_n] = mhi;
            cs[(r + 8) * 4 + warp_n] = shi;
        }
    }
    __syncthreads();

    if (tid < 128) {
        float M = -INFINITY;
        #pragma unroll
        for (int w = 0; w < 4; w++) M = fmaxf(M, cm[tid * 4 + w]);
        float S = 0.0f;
        #pragma unroll
        for (int w = 0; w < 4; w++) {
            float s = cs[tid * 4 + w];
            if (s > 0.0f) S += s * __expf(cm[tid * 4 + w] - M);
        }
        size_t gr = (size_t)(m_tile * TILE_M + tid);
        g_pm[gr * V_TILES + v_tile] = M;
        g_ps[gr * V_TILES + v_tile] = S;
    }
}

// ---------------------------------------------------------------------------
// Kernel 4: one warp per token; single-pass online (M,S) combine.
// Lanes stride over V_TILES partials (coalesced); g_pm read once.
// ---------------------------------------------------------------------------
__global__ void reduce_kernel(const long long* __restrict__ tg) {
    const int tid  = threadIdx.x;
    const int lane = tid & 31;
    const int wib  = tid >> 5;                       // warp in block (0..7)
    const int tok  = blockIdx.x * 8 + wib;           // 1024 blocks x 8 warps

    float nll = 0.0f;
    int valid = 0;
    long long t = tg[tok];
    if (t != IGNORE_INDEX) {
        const float* pm = g_pm + (size_t)tok * V_TILES;
        const float* ps = g_ps + (size_t)tok * V_TILES;
        // single pass: running max M with rescaled sum S
        float M = -INFINITY;
        float S = 0.0f;
        for (int j = lane; j < V_TILES; j += 32) {
            float m = pm[j];
            float s = ps[j];
            if (m > M) {
                S = S * __expf(M - m) + s;   // S==0 when M==-inf: exp(-inf)=0, ok
                M = m;
            } else if (s > 0.0f) {
                S += s * __expf(m - M);
            }
        }
        // warp combine (max then rescaled sum)
        float Mw = M;
        #pragma unroll
        for (int off = 16; off > 0; off >>= 1)
            Mw = fmaxf(Mw, __shfl_xor_sync(0xFFFFFFFFu, Mw, off));
        float Sw = (S > 0.0f) ? S * __expf(M - Mw) : 0.0f;
        #pragma unroll
        for (int off = 16; off > 0; off >>= 1)
            Sw += __shfl_xor_sync(0xFFFFFFFFu, Sw, off);
        nll = Mw + logf(Sw) - g_tgt[tok];
        valid = 1;
    }
    __shared__ float bs[8];
    __shared__ int   bc[8];
    if (lane == 0) { bs[wib] = nll; bc[wib] = valid; }
    __syncthreads();
    if (tid == 0) {
        float s = 0.0f; int c = 0;
        #pragma unroll
        for (int w = 0; w < 8; w++) { s += bs[w]; c += bc[w]; }
        g_bsum[blockIdx.x] = s;
        g_bcnt[blockIdx.x] = c;
    }
}

__global__ void finalize_kernel(float* out) {
    __shared__ float s[1024];
    __shared__ int   c[1024];
    int tid = threadIdx.x;
    s[tid] = g_bsum[tid]; c[tid] = g_bcnt[tid];
    __syncthreads();
    for (int o = 512; o > 0; o >>= 1) {
        if (tid < o) { s[tid] += s[tid + o]; c[tid] += c[tid + o]; }
        __syncthreads();
    }
    if (tid == 0) out[0] = s[0] / (float)max(c[0], 1);
}

// ---------------------------------------------------------------------------
extern "C" void kernel_launch(void* const* d_in, const int* in_sizes, int n_in,
                              void* d_out, int out_size) {
    (void)in_sizes; (void)n_in; (void)out_size;
    const float*     e  = (const float*)d_in[0];
    const float*     c  = (const float*)d_in[1];
    const long long* tg = (const long long*)d_in[2];
    float* out = (float*)d_out;

    static cudaStream_t s2 = nullptr;
    static cudaEvent_t ev_fork = nullptr, ev_join = nullptr;
    if (s2 == nullptr) {
        cudaStreamCreateWithFlags(&s2, cudaStreamNonBlocking);
        cudaEventCreateWithFlags(&ev_fork, cudaEventDisableTiming);
        cudaEventCreateWithFlags(&ev_join, cudaEventDisableTiming);
        cudaFuncSetAttribute(gemm_lse_kernel,
                             cudaFuncAttributeMaxDynamicSharedMemorySize, SMEM_TOTAL);
    }

    // fork: tgt_kernel depends only on raw fp32 inputs -> side stream,
    // overlapping convert + GEMM (GEMM is tensor-bound, DRAM ~1%).
    cudaEventRecord(ev_fork, 0);
    cudaStreamWaitEvent(s2, ev_fork, 0);
    tgt_kernel<<<(N_TOK * 32) / 256, 256, 0, s2>>>(e, c, tg);
    cudaEventRecord(ev_join, s2);

    // main stream: convert -> GEMM
    convert_kernel<<<4096, 256>>>(reinterpret_cast<const float4*>(e),
                                  reinterpret_cast<const float4*>(c));
    gemm_lse_kernel<<<dim3(M_TILES, V_TILES), 256, SMEM_TOTAL>>>();

    // join: reduce needs g_tgt
    cudaStreamWaitEvent(0, ev_join, 0);
    reduce_kernel<<<1024, 256>>>(tg);
    finalize_kernel<<<1, 1024>>>(out);
}